// round 3
// baseline (speedup 1.0000x reference)
#include <cuda_runtime.h>

#define T_LEN 16384
#define DIM   1024
#define NCHUNK 256
#define CLEN   64   // T_LEN / NCHUNK

// ---------------- scratch (static device globals; no allocation) ----------------
__device__ __align__(16) float  g_gain[DIM];
__device__ float2 g_lam[DIM];
__device__ float2 g_lamL[DIM];
__device__ float2 g_carry[NCHUNK * DIM];
__device__ __align__(16) float g_bu_re[(size_t)T_LEN * DIM];  // Bu, then hidden (in-place)
__device__ __align__(16) float g_bu_im[(size_t)T_LEN * DIM];

// ---------------- setup: lambda, lambda^CLEN, gamma gain ----------------
__global__ void setup_kernel(const float* __restrict__ nu_log,
                             const float* __restrict__ theta_log,
                             const float* __restrict__ gamma_log) {
    int h = blockIdx.x * blockDim.x + threadIdx.x;
    if (h >= DIM) return;
    float nu = expf(nu_log[h]);
    float th = expf(theta_log[h]);
    float r  = expf(-nu);
    float lr = r * cosf(th);
    float li = r * sinf(th);
    g_lam[h] = make_float2(lr, li);
    // lambda^64 via 6 squarings
    float ar = lr, ai = li;
#pragma unroll
    for (int s = 0; s < 6; s++) {
        float nr = ar * ar - ai * ai;
        float ni = 2.0f * ar * ai;
        ar = nr; ai = ni;
    }
    g_lamL[h] = make_float2(ar, ai);
    g_gain[h] = expf(gamma_log[h]);
}

// ---------------- GEMM1: Bu = (X * g) @ (B_re, B_im) ----------------
// BM=128, BN=64, BK=16, 256 threads, 8x4 micro-tile, dual accumulator
__global__ __launch_bounds__(256) void gemm_bu(const float* __restrict__ X,
                                               const float* __restrict__ Bre,
                                               const float* __restrict__ Bim) {
    __shared__ float As [16][132];
    __shared__ float Brs[16][68];
    __shared__ float Bis[16][68];

    int tid = threadIdx.x;
    int tx = tid & 15;   // n direction (16 lanes * 4 = 64)
    int ty = tid >> 4;   // m direction (16 lanes * 8 = 128)
    int n0 = blockIdx.x * 64;
    int m0 = blockIdx.y * 128;

    float accr[8][4];
    float acci[8][4];
#pragma unroll
    for (int r = 0; r < 8; r++)
#pragma unroll
        for (int c = 0; c < 4; c++) { accr[r][c] = 0.f; acci[r][c] = 0.f; }

    int arow0 = tid >> 2;          // 0..63 (second half +64)
    int akg   = (tid & 3) * 4;     // k offset within tile
    int brow  = tid >> 4;          // 0..15 (k)
    int bcg   = (tid & 15) * 4;    // n offset

    for (int k0 = 0; k0 < DIM; k0 += 16) {
        // A tile (scaled by gain on the K index), stored transposed As[k][m]
#pragma unroll
        for (int s = 0; s < 2; s++) {
            int row = arow0 + s * 64;
            float4 v = *(const float4*)(X + (size_t)(m0 + row) * DIM + k0 + akg);
            float4 g = *(const float4*)(&g_gain[k0 + akg]);
            As[akg + 0][row] = v.x * g.x;
            As[akg + 1][row] = v.y * g.y;
            As[akg + 2][row] = v.z * g.z;
            As[akg + 3][row] = v.w * g.w;
        }
        // B tiles, direct [k][n]
        *(float4*)(&Brs[brow][bcg]) = *(const float4*)(Bre + (size_t)(k0 + brow) * DIM + n0 + bcg);
        *(float4*)(&Bis[brow][bcg]) = *(const float4*)(Bim + (size_t)(k0 + brow) * DIM + n0 + bcg);
        __syncthreads();

#pragma unroll
        for (int kk = 0; kk < 16; kk++) {
            float4 a0 = *(const float4*)(&As[kk][ty * 8]);
            float4 a1 = *(const float4*)(&As[kk][ty * 8 + 4]);
            float a[8] = {a0.x, a0.y, a0.z, a0.w, a1.x, a1.y, a1.z, a1.w};
            float4 b4r = *(const float4*)(&Brs[kk][tx * 4]);
            float4 b4i = *(const float4*)(&Bis[kk][tx * 4]);
            float br_[4] = {b4r.x, b4r.y, b4r.z, b4r.w};
            float bi_[4] = {b4i.x, b4i.y, b4i.z, b4i.w};
#pragma unroll
            for (int r = 0; r < 8; r++)
#pragma unroll
                for (int c = 0; c < 4; c++) {
                    accr[r][c] = fmaf(a[r], br_[c], accr[r][c]);
                    acci[r][c] = fmaf(a[r], bi_[c], acci[r][c]);
                }
        }
        __syncthreads();
    }

#pragma unroll
    for (int r = 0; r < 8; r++) {
        size_t o = (size_t)(m0 + ty * 8 + r) * DIM + n0 + tx * 4;
        *(float4*)(&g_bu_re[o]) = make_float4(accr[r][0], accr[r][1], accr[r][2], accr[r][3]);
        *(float4*)(&g_bu_im[o]) = make_float4(acci[r][0], acci[r][1], acci[r][2], acci[r][3]);
    }
}

// ---------------- scan pass 1: chunk-local scan (in place), record chunk ends ----------------
__global__ __launch_bounds__(256) void scan_local() {
    int h = blockIdx.y * blockDim.x + threadIdx.x;
    int c = blockIdx.x;
    float2 lam = g_lam[h];
    float ar = 0.f, ai = 0.f;
    size_t idx = (size_t)c * CLEN * DIM + h;
#pragma unroll 4
    for (int t = 0; t < CLEN; t++, idx += DIM) {
        float br = g_bu_re[idx];
        float bi = g_bu_im[idx];
        float nr = fmaf(lam.x, ar, fmaf(-lam.y, ai, br));
        float ni = fmaf(lam.x, ai, fmaf( lam.y, ar, bi));
        ar = nr; ai = ni;
        g_bu_re[idx] = ar;
        g_bu_im[idx] = ai;
    }
    g_carry[c * DIM + h] = make_float2(ar, ai);
}

// ---------------- scan pass 2: prefix over chunk carries (per channel) ----------------
__global__ __launch_bounds__(256) void scan_chunks() {
    int h = blockIdx.x * blockDim.x + threadIdx.x;
    float2 lamL = g_lamL[h];
    float pr = 0.f, pi = 0.f;
    for (int c = 0; c < NCHUNK; c++) {
        float2 e = g_carry[c * DIM + h];
        float nr = fmaf(lamL.x, pr, fmaf(-lamL.y, pi, e.x));
        float ni = fmaf(lamL.x, pi, fmaf( lamL.y, pr, e.y));
        pr = nr; pi = ni;
        g_carry[c * DIM + h] = make_float2(pr, pi);   // inclusive prefix P_c
    }
}

// ---------------- scan pass 3: broadcast carry into chunks 1..NCHUNK-1 ----------------
__global__ __launch_bounds__(256) void scan_apply() {
    int h = blockIdx.y * blockDim.x + threadIdx.x;
    int c = blockIdx.x + 1;                       // chunks 1..255
    float2 P = g_carry[(c - 1) * DIM + h];        // carry-in = prefix of previous chunk
    float2 lam = g_lam[h];
    float fr = lam.x, fi = lam.y;                 // lambda^(t-offset+1)
    size_t idx = (size_t)c * CLEN * DIM + h;
#pragma unroll 4
    for (int t = 0; t < CLEN; t++, idx += DIM) {
        g_bu_re[idx] = fmaf(fr, P.x, fmaf(-fi, P.y, g_bu_re[idx]));
        g_bu_im[idx] = fmaf(fr, P.y, fmaf( fi, P.x, g_bu_im[idx]));
        float nfr = fr * lam.x - fi * lam.y;
        float nfi = fr * lam.y + fi * lam.x;
        fr = nfr; fi = nfi;
    }
}

// ---------------- GEMM2: out = Hr@Cre^T - Hi@Cim^T + X@D ----------------
// BM=128, BN=128, BK=8, 256 threads, 8x8 micro-tile, triple product fused
__global__ __launch_bounds__(256) void gemm_out(const float* __restrict__ X,
                                                const float* __restrict__ Cre,
                                                const float* __restrict__ Cim,
                                                const float* __restrict__ Dm,
                                                float* __restrict__ out) {
    __shared__ float Ahr[8][132];
    __shared__ float Ahi[8][132];
    __shared__ float Ax [8][132];
    __shared__ float Bcr[8][132];
    __shared__ float Bci[8][132];
    __shared__ float Bd [8][132];

    int tid = threadIdx.x;
    int tx = tid & 15;   // n direction (16 * 8 = 128)
    int ty = tid >> 4;   // m direction (16 * 8 = 128)
    int n0 = blockIdx.x * 128;
    int m0 = blockIdx.y * 128;

    float acc[8][8];
#pragma unroll
    for (int r = 0; r < 8; r++)
#pragma unroll
        for (int c = 0; c < 8; c++) acc[r][c] = 0.f;

    int arow = tid >> 1;          // 0..127
    int akg  = (tid & 1) * 4;     // 0 or 4
    int dr   = tid >> 5;          // 0..7
    int dcg  = (tid & 31) * 4;    // 0..124

    for (int k0 = 0; k0 < DIM; k0 += 8) {
        {   // A tiles (Hr, Hi, X), transposed [k][m]
            size_t gi = (size_t)(m0 + arow) * DIM + k0 + akg;
            float4 vr = *(const float4*)(g_bu_re + gi);
            float4 vi = *(const float4*)(g_bu_im + gi);
            float4 vx = *(const float4*)(X + gi);
            Ahr[akg + 0][arow] = vr.x; Ahr[akg + 1][arow] = vr.y;
            Ahr[akg + 2][arow] = vr.z; Ahr[akg + 3][arow] = vr.w;
            Ahi[akg + 0][arow] = vi.x; Ahi[akg + 1][arow] = vi.y;
            Ahi[akg + 2][arow] = vi.z; Ahi[akg + 3][arow] = vi.w;
            Ax [akg + 0][arow] = vx.x; Ax [akg + 1][arow] = vx.y;
            Ax [akg + 2][arow] = vx.z; Ax [akg + 3][arow] = vx.w;
        }
        {   // C tiles: C[o,k] -> Bs[k][n] (transposed load)
            size_t gi = (size_t)(n0 + arow) * DIM + k0 + akg;
            float4 vr = *(const float4*)(Cre + gi);
            float4 vi = *(const float4*)(Cim + gi);
            Bcr[akg + 0][arow] = vr.x; Bcr[akg + 1][arow] = vr.y;
            Bcr[akg + 2][arow] = vr.z; Bcr[akg + 3][arow] = vr.w;
            Bci[akg + 0][arow] = vi.x; Bci[akg + 1][arow] = vi.y;
            Bci[akg + 2][arow] = vi.z; Bci[akg + 3][arow] = vi.w;
        }
        // D tile: D[k,n] direct
        *(float4*)(&Bd[dr][dcg]) = *(const float4*)(Dm + (size_t)(k0 + dr) * DIM + n0 + dcg);
        __syncthreads();

#pragma unroll
        for (int kk = 0; kk < 8; kk++) {
            float4 h0 = *(const float4*)(&Ahr[kk][ty * 8]);
            float4 h1 = *(const float4*)(&Ahr[kk][ty * 8 + 4]);
            float4 i0 = *(const float4*)(&Ahi[kk][ty * 8]);
            float4 i1 = *(const float4*)(&Ahi[kk][ty * 8 + 4]);
            float4 x0 = *(const float4*)(&Ax [kk][ty * 8]);
            float4 x1 = *(const float4*)(&Ax [kk][ty * 8 + 4]);
            float ahr[8] = {h0.x, h0.y, h0.z, h0.w, h1.x, h1.y, h1.z, h1.w};
            float ahi[8] = {i0.x, i0.y, i0.z, i0.w, i1.x, i1.y, i1.z, i1.w};
            float ax [8] = {x0.x, x0.y, x0.z, x0.w, x1.x, x1.y, x1.z, x1.w};

            float4 c0 = *(const float4*)(&Bcr[kk][tx * 8]);
            float4 c1 = *(const float4*)(&Bcr[kk][tx * 8 + 4]);
            float4 s0 = *(const float4*)(&Bci[kk][tx * 8]);
            float4 s1 = *(const float4*)(&Bci[kk][tx * 8 + 4]);
            float4 d0 = *(const float4*)(&Bd [kk][tx * 8]);
            float4 d1 = *(const float4*)(&Bd [kk][tx * 8 + 4]);
            float bcr[8] = {c0.x, c0.y, c0.z, c0.w, c1.x, c1.y, c1.z, c1.w};
            float bci[8] = {s0.x, s0.y, s0.z, s0.w, s1.x, s1.y, s1.z, s1.w};
            float bd [8] = {d0.x, d0.y, d0.z, d0.w, d1.x, d1.y, d1.z, d1.w};

#pragma unroll
            for (int r = 0; r < 8; r++)
#pragma unroll
                for (int c = 0; c < 8; c++) {
                    float v = acc[r][c];
                    v = fmaf(ahr[r],  bcr[c], v);
                    v = fmaf(-ahi[r], bci[c], v);
                    v = fmaf(ax[r],   bd[c],  v);
                    acc[r][c] = v;
                }
        }
        __syncthreads();
    }

#pragma unroll
    for (int r = 0; r < 8; r++) {
        size_t o = (size_t)(m0 + ty * 8 + r) * DIM + n0 + tx * 8;
        *(float4*)(&out[o])     = make_float4(acc[r][0], acc[r][1], acc[r][2], acc[r][3]);
        *(float4*)(&out[o + 4]) = make_float4(acc[r][4], acc[r][5], acc[r][6], acc[r][7]);
    }
}

// ---------------- launch ----------------
extern "C" void kernel_launch(void* const* d_in, const int* in_sizes, int n_in,
                              void* d_out, int out_size) {
    const float* X         = (const float*)d_in[0];
    const float* nu_log    = (const float*)d_in[1];
    const float* theta_log = (const float*)d_in[2];
    const float* gamma_log = (const float*)d_in[3];
    const float* Bre       = (const float*)d_in[4];
    const float* Bim       = (const float*)d_in[5];
    const float* Cre       = (const float*)d_in[6];
    const float* Cim       = (const float*)d_in[7];
    const float* Dm        = (const float*)d_in[8];
    float* out             = (float*)d_out;

    setup_kernel<<<4, 256>>>(nu_log, theta_log, gamma_log);
    gemm_bu<<<dim3(DIM / 64, T_LEN / 128), 256>>>(X, Bre, Bim);
    scan_local<<<dim3(NCHUNK, DIM / 256), 256>>>();
    scan_chunks<<<DIM / 256, 256>>>();
    scan_apply<<<dim3(NCHUNK - 1, DIM / 256), 256>>>();
    gemm_out<<<dim3(DIM / 128, T_LEN / 128), 256>>>(X, Cre, Cim, Dm, out);
}

// round 5
// speedup vs baseline: 4.3241x; 4.3241x over previous
#include <cuda_runtime.h>
#include <cuda_bf16.h>
#include <cstdint>

#define T_LEN 16384
#define DIM   1024
#define NCHUNK 256
#define CLEN   64

// ---------------- scratch (static device globals; no allocation) ----------------
__device__ __align__(16) float  g_gain[DIM];
__device__ float2 g_lam[DIM];
__device__ float2 g_lamL[DIM];
__device__ float2 g_carry [NCHUNK * DIM];
__device__ float2 g_carry2[NCHUNK * DIM];
__device__ __align__(16) float g_bu_re[(size_t)T_LEN * DIM];
__device__ __align__(16) float g_bu_im[(size_t)T_LEN * DIM];

// bf16 operands (all K-major: [row][k], k contiguous)
__device__ __align__(16) __nv_bfloat16 g_x_hi  [(size_t)T_LEN * DIM];
__device__ __align__(16) __nv_bfloat16 g_x_lo  [(size_t)T_LEN * DIM];
__device__ __align__(16) __nv_bfloat16 g_hre_hi[(size_t)T_LEN * DIM];
__device__ __align__(16) __nv_bfloat16 g_him_hi[(size_t)T_LEN * DIM];
__device__ __align__(16) __nv_bfloat16 g_brt_hi[DIM * DIM];   // (B_re*gain)^T  [h][i]
__device__ __align__(16) __nv_bfloat16 g_bit_hi[DIM * DIM];   // (B_im*gain)^T  [h][i]
__device__ __align__(16) __nv_bfloat16 g_cre_hi[DIM * DIM];   // C_re           [o][h]
__device__ __align__(16) __nv_bfloat16 g_cin_hi[DIM * DIM];   // -C_im          [o][h]
__device__ __align__(16) __nv_bfloat16 g_dt_hi [DIM * DIM];   // D^T            [o][i]
__device__ __align__(16) __nv_bfloat16 g_dt_lo [DIM * DIM];

// ---------------- PTX helpers (base sm_80+ ISA only: mma.sync / ldmatrix / cp.async) ----------------
__device__ __forceinline__ unsigned smem_u32(const void* p) {
    unsigned a;
    asm("{ .reg .u64 t; cvta.to.shared.u64 t, %1; cvt.u32.u64 %0, t; }" : "=r"(a) : "l"(p));
    return a;
}
__device__ __forceinline__ void ldsm4(uint32_t* r, unsigned a) {
    asm volatile("ldmatrix.sync.aligned.m8n8.x4.shared.b16 {%0,%1,%2,%3}, [%4];"
        : "=r"(r[0]), "=r"(r[1]), "=r"(r[2]), "=r"(r[3]) : "r"(a));
}
__device__ __forceinline__ void mma16816(float* c, const uint32_t* a, uint32_t b0, uint32_t b1) {
    asm volatile(
        "mma.sync.aligned.m16n8k16.row.col.f32.bf16.bf16.f32 "
        "{%0,%1,%2,%3}, {%4,%5,%6,%7}, {%8,%9}, {%0,%1,%2,%3};"
        : "+f"(c[0]), "+f"(c[1]), "+f"(c[2]), "+f"(c[3])
        : "r"(a[0]), "r"(a[1]), "r"(a[2]), "r"(a[3]), "r"(b0), "r"(b1));
}
__device__ __forceinline__ void cp16(unsigned dst, const void* src) {
    asm volatile("cp.async.cg.shared.global [%0], [%1], 16;" :: "r"(dst), "l"(src) : "memory");
}
#define CP_COMMIT() asm volatile("cp.async.commit_group;" ::: "memory")
#define CP_WAIT1()  asm volatile("cp.async.wait_group 1;" ::: "memory")

// ---------------- setup ----------------
__global__ void setup_kernel(const float* __restrict__ nu_log,
                             const float* __restrict__ theta_log,
                             const float* __restrict__ gamma_log) {
    int h = blockIdx.x * blockDim.x + threadIdx.x;
    if (h >= DIM) return;
    float nu = expf(nu_log[h]);
    float th = expf(theta_log[h]);
    float r  = expf(-nu);
    float lr = r * cosf(th);
    float li = r * sinf(th);
    g_lam[h] = make_float2(lr, li);
    float ar = lr, ai = li;
#pragma unroll
    for (int s = 0; s < 6; s++) {
        float nr = ar * ar - ai * ai;
        float ni = 2.0f * ar * ai;
        ar = nr; ai = ni;
    }
    g_lamL[h] = make_float2(ar, ai);
    g_gain[h] = expf(gamma_log[h]);
}

// ---------------- prep: elementwise split ----------------
// mode 0: X -> hi+lo, 1: Cre -> hi, 2: -Cim -> hi
__global__ __launch_bounds__(256) void split_mat(const float* __restrict__ src, int mode, int n) {
    int i = (blockIdx.x * blockDim.x + threadIdx.x) * 4;
    if (i >= n) return;
    float4 v = *(const float4*)(src + i);
    float sign = (mode == 2) ? -1.0f : 1.0f;
    float vv[4] = {v.x * sign, v.y * sign, v.z * sign, v.w * sign};
    __nv_bfloat16 h4[4], l4[4];
#pragma unroll
    for (int j = 0; j < 4; j++) {
        __nv_bfloat16 h = __float2bfloat16(vv[j]);
        h4[j] = h;
        l4[j] = __float2bfloat16(vv[j] - __bfloat162float(h));
    }
    __nv_bfloat16* hi = (mode == 0) ? g_x_hi : (mode == 1 ? g_cre_hi : g_cin_hi);
    *(uint2*)(hi + i) = *(uint2*)h4;
    if (mode == 0) *(uint2*)(g_x_lo + i) = *(uint2*)l4;
}

// ---------------- prep: transpose + split (gain-scaled B_re/B_im; D hi+lo) ----------------
__global__ void transpose_split(const float* __restrict__ src, int mode) {
    __shared__ float tl[32][33];
    int bx = blockIdx.x * 32, by = blockIdx.y * 32;
    int tx = threadIdx.x, ty = threadIdx.y;
    bool use_gain = (mode != 2);
#pragma unroll
    for (int r = 0; r < 4; r++) {
        int row = by + ty + r * 8;
        float v = src[(size_t)row * DIM + bx + tx];
        if (use_gain) v *= g_gain[row];
        tl[ty + r * 8][tx] = v;
    }
    __syncthreads();
    __nv_bfloat16* hi = (mode == 0) ? g_brt_hi : (mode == 1 ? g_bit_hi : g_dt_hi);
#pragma unroll
    for (int r = 0; r < 4; r++) {
        float v = tl[tx][ty + r * 8];
        __nv_bfloat16 h = __float2bfloat16(v);
        size_t o = (size_t)(bx + ty + r * 8) * DIM + by + tx;
        hi[o] = h;
        if (mode == 2) g_dt_lo[o] = __float2bfloat16(v - __bfloat162float(h));
    }
}

// ---------------- generic TN bf16 GEMM with register-accumulated pass list ----------------
// C[m][n] = sum_passes A_p[m][k] * B_p[n][k], BM=BN=128, BK=64, 256 threads.
// smem per stage: A 16KB + B 16KB, SW128 swizzle, 2 stages = 64KB dynamic.

__device__ __forceinline__ void pass_ptrs(int mode, int z, int kt,
        const __nv_bfloat16*& A, const __nv_bfloat16*& B, int& k0) {
    if (mode == 0) {
        A = g_x_hi; B = z ? g_bit_hi : g_brt_hi; k0 = kt * 64;
    } else {
        int p = kt >> 4; k0 = (kt & 15) * 64;
        switch (p) {
            case 0:  A = g_hre_hi; B = g_cre_hi; break;
            case 1:  A = g_him_hi; B = g_cin_hi; break;
            case 2:  A = g_x_hi;   B = g_dt_hi;  break;
            case 3:  A = g_x_hi;   B = g_dt_lo;  break;
            default: A = g_x_lo;   B = g_dt_hi;  break;
        }
    }
}

__device__ __forceinline__ void load_stage(unsigned sA, unsigned sB,
        const __nv_bfloat16* Ag, const __nv_bfloat16* Bg,
        int m0, int n0, int k0, int tid) {
#pragma unroll
    for (int i = 0; i < 4; i++) {
        int idx = tid + i * 256;
        int row = idx >> 3, g = idx & 7;
        unsigned sw = (unsigned)(row * 128 + ((g ^ (row & 7)) << 4));
        cp16(sA + sw, Ag + (size_t)(m0 + row) * DIM + k0 + g * 8);
        cp16(sB + sw, Bg + (size_t)(n0 + row) * DIM + k0 + g * 8);
    }
}

__device__ __forceinline__ void compute_stage(unsigned sA, unsigned sB,
        int wm, int wn, int lane, float c[4][4][4]) {
    const int lr = lane & 15, lh = lane >> 4;
#pragma unroll
    for (int ks = 0; ks < 4; ks++) {
        uint32_t a[4][4];
#pragma unroll
        for (int mf = 0; mf < 4; mf++) {
            int row = wm * 64 + mf * 16 + lr;
            int kg = ks * 2 + lh;
            ldsm4(a[mf], sA + row * 128 + ((kg ^ (row & 7)) << 4));
        }
        uint32_t bb[2][4];
#pragma unroll
        for (int nh = 0; nh < 2; nh++) {
            int row = wn * 32 + nh * 16 + lr;
            int kg = ks * 2 + lh;
            ldsm4(bb[nh], sB + row * 128 + ((kg ^ (row & 7)) << 4));
        }
#pragma unroll
        for (int mf = 0; mf < 4; mf++) {
            mma16816(c[mf][0], a[mf], bb[0][0], bb[0][2]);
            mma16816(c[mf][1], a[mf], bb[0][1], bb[0][3]);
            mma16816(c[mf][2], a[mf], bb[1][0], bb[1][2]);
            mma16816(c[mf][3], a[mf], bb[1][1], bb[1][3]);
        }
    }
}

__global__ __launch_bounds__(256) void gemm_mma(int mode, float* __restrict__ outp) {
    extern __shared__ __align__(128) char sm[];
    unsigned sbase = smem_u32(sm);
    const int tid = threadIdx.x, lane = tid & 31, w = tid >> 5;
    const int wm = w & 1, wn = w >> 1;
    const int n0 = blockIdx.x * 128, m0 = blockIdx.y * 128;
    const int z  = blockIdx.z;
    const int NK = (mode == 0) ? 16 : 80;

    float c[4][4][4];
#pragma unroll
    for (int a = 0; a < 4; a++)
#pragma unroll
        for (int b = 0; b < 4; b++)
#pragma unroll
            for (int d = 0; d < 4; d++) c[a][b][d] = 0.f;

    {
        const __nv_bfloat16 *A, *B; int k0;
        pass_ptrs(mode, z, 0, A, B, k0);
        load_stage(sbase, sbase + 16384, A, B, m0, n0, k0, tid);
        CP_COMMIT();
        pass_ptrs(mode, z, 1, A, B, k0);
        load_stage(sbase + 32768, sbase + 49152, A, B, m0, n0, k0, tid);
        CP_COMMIT();
    }

    for (int kt = 0; kt < NK; kt++) {
        CP_WAIT1();
        __syncthreads();
        unsigned st = sbase + (kt & 1) * 32768;
        compute_stage(st, st + 16384, wm, wn, lane, c);
        __syncthreads();
        if (kt + 2 < NK) {
            const __nv_bfloat16 *A, *B; int k0;
            pass_ptrs(mode, z, kt + 2, A, B, k0);
            unsigned sd = sbase + (kt & 1) * 32768;
            load_stage(sd, sd + 16384, A, B, m0, n0, k0, tid);
        }
        CP_COMMIT();
    }

    float* dst = (mode == 0) ? (z ? g_bu_im : g_bu_re) : outp;
#pragma unroll
    for (int mf = 0; mf < 4; mf++) {
#pragma unroll
        for (int nf = 0; nf < 4; nf++) {
            int r   = wm * 64 + mf * 16 + (lane >> 2);
            int col = wn * 32 + nf * 8  + (lane & 3) * 2;
            size_t o = (size_t)(m0 + r) * DIM + n0 + col;
            float2 v01 = make_float2(c[mf][nf][0], c[mf][nf][1]);
            float2 v23 = make_float2(c[mf][nf][2], c[mf][nf][3]);
            *(float2*)(dst + o) = v01;
            *(float2*)(dst + o + 8 * DIM) = v23;
        }
    }
}

// ---------------- scan pass 1: chunk-local scan (in place) ----------------
__global__ __launch_bounds__(256) void scan_local() {
    int h = blockIdx.y * blockDim.x + threadIdx.x;
    int c = blockIdx.x;
    float2 lam = g_lam[h];
    float ar = 0.f, ai = 0.f;
    size_t idx = (size_t)c * CLEN * DIM + h;
#pragma unroll 4
    for (int t = 0; t < CLEN; t++, idx += DIM) {
        float br = g_bu_re[idx];
        float bi = g_bu_im[idx];
        float nr = fmaf(lam.x, ar, fmaf(-lam.y, ai, br));
        float ni = fmaf(lam.x, ai, fmaf( lam.y, ar, bi));
        ar = nr; ai = ni;
        g_bu_re[idx] = ar;
        g_bu_im[idx] = ai;
    }
    g_carry[c * DIM + h] = make_float2(ar, ai);
}

// ---------------- scan pass 2: prefix over chunk carries ----------------
__global__ __launch_bounds__(256) void scan_chunks() {
    int h = blockIdx.x * blockDim.x + threadIdx.x;
    float2 lamL = g_lamL[h];
    float pr = 0.f, pi = 0.f;
#pragma unroll 4
    for (int c = 0; c < NCHUNK; c++) {
        float2 e = g_carry[c * DIM + h];
        float nr = fmaf(lamL.x, pr, fmaf(-lamL.y, pi, e.x));
        float ni = fmaf(lamL.x, pi, fmaf( lamL.y, pr, e.y));
        pr = nr; pi = ni;
        g_carry2[c * DIM + h] = make_float2(pr, pi);
    }
}

// ---------------- scan pass 3: apply carry, emit bf16 H (hi only) ----------------
__global__ __launch_bounds__(256) void scan_apply_all() {
    int h = blockIdx.y * blockDim.x + threadIdx.x;
    int c = blockIdx.x;
    float2 P = (c == 0) ? make_float2(0.f, 0.f) : g_carry2[(c - 1) * DIM + h];
    float2 lam = g_lam[h];
    float fr = lam.x, fi = lam.y;
    size_t idx = (size_t)c * CLEN * DIM + h;
#pragma unroll 4
    for (int t = 0; t < CLEN; t++, idx += DIM) {
        float hr = fmaf(fr, P.x, fmaf(-fi, P.y, g_bu_re[idx]));
        float hi = fmaf(fr, P.y, fmaf( fi, P.x, g_bu_im[idx]));
        g_hre_hi[idx] = __float2bfloat16(hr);
        g_him_hi[idx] = __float2bfloat16(hi);
        float nfr = fr * lam.x - fi * lam.y;
        float nfi = fr * lam.y + fi * lam.x;
        fr = nfr; fi = nfi;
    }
}

// ---------------- launch ----------------
extern "C" void kernel_launch(void* const* d_in, const int* in_sizes, int n_in,
                              void* d_out, int out_size) {
    const float* X         = (const float*)d_in[0];
    const float* nu_log    = (const float*)d_in[1];
    const float* theta_log = (const float*)d_in[2];
    const float* gamma_log = (const float*)d_in[3];
    const float* Bre       = (const float*)d_in[4];
    const float* Bim       = (const float*)d_in[5];
    const float* Cre       = (const float*)d_in[6];
    const float* Cim       = (const float*)d_in[7];
    const float* Dm        = (const float*)d_in[8];
    float* out             = (float*)d_out;

    cudaFuncSetAttribute(gemm_mma, cudaFuncAttributeMaxDynamicSharedMemorySize, 65536);

    setup_kernel<<<4, 256>>>(nu_log, theta_log, gamma_log);
    split_mat<<<T_LEN * DIM / 4 / 256, 256>>>(X, 0, T_LEN * DIM);
    split_mat<<<DIM * DIM / 4 / 256, 256>>>(Cre, 1, DIM * DIM);
    split_mat<<<DIM * DIM / 4 / 256, 256>>>(Cim, 2, DIM * DIM);
    transpose_split<<<dim3(32, 32), dim3(32, 8)>>>(Bre, 0);
    transpose_split<<<dim3(32, 32), dim3(32, 8)>>>(Bim, 1);
    transpose_split<<<dim3(32, 32), dim3(32, 8)>>>(Dm, 2);

    // GEMM1: Bu_re / Bu_im via blockIdx.z
    gemm_mma<<<dim3(DIM / 128, T_LEN / 128, 2), 256, 65536>>>(0, nullptr);

    scan_local<<<dim3(NCHUNK, DIM / 256), 256>>>();
    scan_chunks<<<DIM / 256, 256>>>();
    scan_apply_all<<<dim3(NCHUNK, DIM / 256), 256>>>();

    // GEMM2: out = Hr@Cre^T + Hi@(-Cim)^T + X@D   (5 register-accumulated passes)
    gemm_mma<<<dim3(DIM / 128, T_LEN / 128, 1), 256, 65536>>>(1, out);
}